// round 1
// baseline (speedup 1.0000x reference)
#include <cuda_runtime.h>

#define Dd       128
#define NODES    68
#define NREG     9
#define NTOT     77
#define NPAD     80
#define ADJS     80
#define CK       32
#define NTHREADS 512
#define NWARPS   16
#define RN       5    // 16 warps * 5 rows = 80 padded rows

typedef unsigned long long ull;

__constant__ int2 c_regions[9] = {
  {0,16},{17,21},{22,26},{27,30},{31,35},{36,41},{42,47},{48,59},{60,67}
};

__device__ __forceinline__ void fma2(ull &acc, ull a, ull b){
  asm("fma.rn.f32x2 %0, %1, %2, %0;" : "+l"(acc) : "l"(a), "l"(b));
}
__device__ __forceinline__ ull pack2(float x, float y){
  ull r; asm("mov.b64 %0, {%1, %2};" : "=l"(r) : "f"(x), "f"(y)); return r;
}
__device__ __forceinline__ float2 unpack2(ull v){
  float2 f; asm("mov.b64 {%0, %1}, %2;" : "=f"(f.x), "=f"(f.y) : "l"(v)); return f;
}
__device__ __forceinline__ void cp16(void* s, const void* g){
  unsigned sa = (unsigned)__cvta_generic_to_shared(s);
  asm volatile("cp.async.cg.shared.global [%0], [%1], 16;" :: "r"(sa), "l"(g));
}

// shared memory layout (float offsets)
#define SX_OFF   0
#define SAD_OFF  (NPAD*Dd)                   // ull[NPAD*Dd]   (agg, duplicated pairs)
#define SADJ_OFF (SAD_OFF + 2*NPAD*Dd)       // ull[NPAD*ADJS] (adj, duplicated pairs)
#define SWB_OFF  (SADJ_OFF + 2*NPAD*ADJS)    // float[2*CK*Dd] (W double buffer)
#define SWR_OFF  (SWB_OFF + 2*CK*Dd)
#define SB_OFF   (SWR_OFF + Dd)
#define SG_OFF   (SB_OFF + Dd)
#define SBE_OFF  (SG_OFF + Dd)
#define SS_OFF   (SBE_OFF + Dd)
#define SW_OFF   (SS_OFF + NPAD)
#define SMEM_FLOATS (SW_OFF + NPAD)          // 52384 floats = 209536 bytes

__global__ void __launch_bounds__(NTHREADS, 1)
net_kernel(const float* __restrict__ lm, const float* __restrict__ adj,
           const float* __restrict__ Wr, const float* __restrict__ br,
           const float* __restrict__ W0, const float* __restrict__ b0,
           const float* __restrict__ W1, const float* __restrict__ b1,
           const float* __restrict__ W2, const float* __restrict__ b2,
           const float* __restrict__ W3, const float* __restrict__ b3,
           const float* __restrict__ gamma, const float* __restrict__ beta,
           float* __restrict__ out)
{
  extern __shared__ float sm[];
  float* sx   = sm + SX_OFF;
  ull*   sad  = (ull*)(sm + SAD_OFF);
  ull*   sadj = (ull*)(sm + SADJ_OFF);
  float* swb  = sm + SWB_OFF;
  float* sWr  = sm + SWR_OFF;
  float* sb   = sm + SB_OFF;
  float* sg   = sm + SG_OFF;
  float* sbe  = sm + SBE_OFF;
  float* ss   = sm + SS_OFF;
  float* sw   = sm + SW_OFF;

  const int tid  = threadIdx.x;
  const int lane = tid & 31;
  const int warp = tid >> 5;
  const int g    = blockIdx.x;          // b*T + t

  // ---- load adj (duplicated pairs), pad rows 77..79 with zeros ----
  for (int i = tid; i < NTOT*NTOT; i += NTHREADS){
    int n = i / NTOT, m = i - n*NTOT;
    float v = adj[i];
    sadj[n*ADJS + m] = pack2(v, v);
  }
  for (int i = tid; i < 3*ADJS; i += NTHREADS)
    sadj[NTOT*ADJS + i] = 0ull;

  // ---- load lm tile into sx rows [0,68) ----
  {
    const float4* src = (const float4*)(lm + (size_t)g * (NODES*Dd));
    float4* dst = (float4*)sx;
    for (int i = tid; i < NODES*Dd/4; i += NTHREADS) dst[i] = src[i];
  }
  for (int i = tid; i < 3*Dd; i += NTHREADS) sx[NTOT*Dd + i] = 0.f;
  if (tid < Dd){ sWr[tid] = Wr[tid]; sg[tid] = gamma[tid]; sbe[tid] = beta[tid]; }
  __syncthreads();

  // ---- region-pool scores: s[n] = lm[n,:]·Wr + br ----
  {
    const float brv = __ldg(br);
    const float4 wv = ((const float4*)sWr)[lane];
    for (int n = warp; n < NODES; n += NWARPS){
      float4 xv = ((const float4*)(sx + n*Dd))[lane];
      float d = xv.x*wv.x + xv.y*wv.y + xv.z*wv.z + xv.w*wv.w;
      #pragma unroll
      for (int o = 16; o; o >>= 1) d += __shfl_xor_sync(0xffffffffu, d, o);
      if (lane == 0) ss[n] = d + brv;
    }
  }
  __syncthreads();

  // ---- per-region softmax weights ----
  if (tid < NREG){
    int2 re = c_regions[tid];
    float mx = -3.4e38f;
    for (int n = re.x; n <= re.y; n++) mx = fmaxf(mx, ss[n]);
    float sum = 0.f;
    for (int n = re.x; n <= re.y; n++){ float e = expf(ss[n]-mx); sw[n] = e; sum += e; }
    float inv = 1.f/sum;
    for (int n = re.x; n <= re.y; n++) sw[n] *= inv;
  }
  __syncthreads();

  // ---- pooled global nodes -> sx rows [68,77) ----
  for (int i = tid; i < NREG*Dd; i += NTHREADS){
    int r = i >> 7, d = i & (Dd-1);
    int2 re = c_regions[r];
    float acc = 0.f;
    for (int n = re.x; n <= re.y; n++) acc = fmaf(sw[n], sx[n*Dd + d], acc);
    sx[(NODES + r)*Dd + d] = acc;
  }
  __syncthreads();

  const float* Ws[4] = {W0, W1, W2, W3};
  const float* Bs[4] = {b0, b1, b2, b3};
  const int nbase = warp * RN;

  #pragma unroll 1
  for (int layer = 0; layer < 4; layer++){
    const float* W = Ws[layer];

    // prefetch W chunk 0 -> buffer 0 (overlaps with phase 1)
    #pragma unroll
    for (int i = 0; i < (CK*Dd/4)/NTHREADS; i++){
      int idx = tid + i*NTHREADS;
      cp16(swb + idx*4, W + idx*4);
    }
    asm volatile("cp.async.commit_group;");
    if (tid < Dd) sb[tid] = Bs[layer][tid];

    // ---- phase 1: agg = adj @ x (warp-private rows, d-pairs via FFMA2) ----
    ull acc0[RN], acc1[RN];
    #pragma unroll
    for (int r = 0; r < RN; r++){ acc0[r] = 0ull; acc1[r] = 0ull; }
    {
      const ull* xp = (const ull*)sx + lane*2;     // row stride Dd/2 ulls
      const ull* ap = sadj + nbase*ADJS;
      #pragma unroll 7
      for (int m = 0; m < NTOT; m++){
        ull x01 = xp[m*(Dd/2)];
        ull x23 = xp[m*(Dd/2) + 1];
        #pragma unroll
        for (int r = 0; r < RN; r++){
          ull a = ap[r*ADJS + m];
          fma2(acc0[r], a, x01);
          fma2(acc1[r], a, x23);
        }
      }
      // store agg duplicated (broadcast-ready for phase 2)
      #pragma unroll
      for (int r = 0; r < RN; r++){
        float2 v01 = unpack2(acc0[r]);
        float2 v23 = unpack2(acc1[r]);
        ull* o = sad + (nbase + r)*Dd + lane*4;
        o[0] = pack2(v01.x, v01.x);
        o[1] = pack2(v01.y, v01.y);
        o[2] = pack2(v23.x, v23.x);
        o[3] = pack2(v23.y, v23.y);
      }
    }

    // ---- phase 2: x = relu(agg @ W + b) (+ residual) ----
    #pragma unroll
    for (int r = 0; r < RN; r++){ acc0[r] = 0ull; acc1[r] = 0ull; }
    #pragma unroll 1
    for (int kc = 0; kc < Dd/CK; kc++){
      asm volatile("cp.async.wait_group 0;");
      __syncthreads();
      if (kc + 1 < Dd/CK){
        float* dst = swb + ((kc+1)&1)*(CK*Dd);
        const float* src = W + (kc+1)*(CK*Dd);
        #pragma unroll
        for (int i = 0; i < (CK*Dd/4)/NTHREADS; i++){
          int idx = tid + i*NTHREADS;
          cp16(dst + idx*4, src + idx*4);
        }
        asm volatile("cp.async.commit_group;");
      }
      const ull* wp  = (const ull*)(swb + (kc&1)*(CK*Dd)) + lane*2;
      const ull* apk = sad + nbase*Dd + kc*CK;
      #pragma unroll 8
      for (int k = 0; k < CK; k++){
        ull w01 = wp[k*(Dd/2)];
        ull w23 = wp[k*(Dd/2) + 1];
        #pragma unroll
        for (int r = 0; r < RN; r++){
          ull a = apk[r*Dd + k];
          fma2(acc0[r], a, w01);
          fma2(acc1[r], a, w23);
        }
      }
    }

    // epilogue: bias + relu + residual, write back into sx
    {
      const float4 bv = ((const float4*)sb)[lane];
      #pragma unroll
      for (int r = 0; r < RN; r++){
        int n = nbase + r;
        float2 v01 = unpack2(acc0[r]);
        float2 v23 = unpack2(acc1[r]);
        float o0 = fmaxf(v01.x + bv.x, 0.f);
        float o1 = fmaxf(v01.y + bv.y, 0.f);
        float o2 = fmaxf(v23.x + bv.z, 0.f);
        float o3 = fmaxf(v23.y + bv.w, 0.f);
        float4* xr = (float4*)(sx + n*Dd) + lane;
        if (layer < 3){
          float4 res = *xr;
          o0 += res.x; o1 += res.y; o2 += res.z; o3 += res.w;
        }
        *xr = make_float4(o0, o1, o2, o3);
      }
    }
    __syncthreads();
  }

  // ---- LayerNorm over D + writeout ----
  {
    const float4 gv  = ((const float4*)sg)[lane];
    const float4 bev = ((const float4*)sbe)[lane];
    for (int n = warp; n < NTOT; n += NWARPS){
      float4 v = ((const float4*)(sx + n*Dd))[lane];
      float s  = v.x + v.y + v.z + v.w;
      float s2 = v.x*v.x + v.y*v.y + v.z*v.z + v.w*v.w;
      #pragma unroll
      for (int o = 16; o; o >>= 1){
        s  += __shfl_xor_sync(0xffffffffu, s,  o);
        s2 += __shfl_xor_sync(0xffffffffu, s2, o);
      }
      float mu  = s * (1.f/Dd);
      float var = s2 * (1.f/Dd) - mu*mu;
      float inv = rsqrtf(var + 1e-5f);
      float4 o4;
      o4.x = (v.x - mu)*inv*gv.x + bev.x;
      o4.y = (v.y - mu)*inv*gv.y + bev.y;
      o4.z = (v.z - mu)*inv*gv.z + bev.z;
      o4.w = (v.w - mu)*inv*gv.w + bev.w;
      ((float4*)(out + ((size_t)g*NTOT + n)*Dd))[lane] = o4;
    }
  }
}

extern "C" void kernel_launch(void* const* d_in, const int* in_sizes, int n_in,
                              void* d_out, int out_size)
{
  const float* lm    = (const float*)d_in[0];
  const float* adj   = (const float*)d_in[1];
  const float* Wr    = (const float*)d_in[2];
  const float* br    = (const float*)d_in[3];
  const float* W0    = (const float*)d_in[4];
  const float* b0    = (const float*)d_in[5];
  const float* W1    = (const float*)d_in[6];
  const float* b1    = (const float*)d_in[7];
  const float* W2    = (const float*)d_in[8];
  const float* b2    = (const float*)d_in[9];
  const float* W3    = (const float*)d_in[10];
  const float* b3    = (const float*)d_in[11];
  const float* gamma = (const float*)d_in[12];
  const float* beta  = (const float*)d_in[13];
  float* out = (float*)d_out;

  const size_t smem = (size_t)SMEM_FLOATS * sizeof(float);
  cudaFuncSetAttribute(net_kernel, cudaFuncAttributeMaxDynamicSharedMemorySize, (int)smem);
  net_kernel<<<32*128, NTHREADS, smem>>>(lm, adj, Wr, br,
                                         W0, b0, W1, b1, W2, b2, W3, b3,
                                         gamma, beta, out);
}